// round 17
// baseline (speedup 1.0000x reference)
#include <cuda_runtime.h>
#include <cuda_fp16.h>
#include <math.h>

// ---------------------------------------------------------------------------
// Problem constants
// ---------------------------------------------------------------------------
#define BATCH 8
#define SEQ 1024
#define DMODEL 1024
#define NHEAD 16
#define HDIM 64
#define DFF 4096
#define NTOK (BATCH * SEQ)          // 8192 rows
#define QKV3 (3 * DMODEL)           // 3072

// ---------------------------------------------------------------------------
// Scratch buffers (device globals: allocation-free)
// ---------------------------------------------------------------------------
__device__ __half g_xn1h[NTOK * DMODEL];
__device__ float  g_xn1f[NTOK * DMODEL];
__device__ __half g_qkvh[NTOK * QKV3];
__device__ __half g_atth[NTOK * DMODEL];
__device__ float  g_x2  [NTOK * DMODEL];
__device__ __half g_xn2h[NTOK * DMODEL];
__device__ float  g_xn2f[NTOK * DMODEL];
__device__ __half g_hbh [NTOK * DFF];
// k-pair-interleaved fp16 weights: word (kp, n) = {W[2kp][n], W[2kp+1][n]}
__device__ unsigned g_wqkv_i[(DMODEL / 2) * QKV3];
__device__ unsigned g_wproj_i[(DMODEL / 2) * DMODEL];
__device__ unsigned g_w1_i[(DMODEL / 2) * DFF];
__device__ unsigned g_w2_i[(DFF / 2) * DMODEL];

// ---------------------------------------------------------------------------
// helpers
// ---------------------------------------------------------------------------
__device__ __forceinline__ void mma_fp16(float* d, const unsigned* a, const unsigned* b) {
    asm volatile(
        "mma.sync.aligned.m16n8k16.row.col.f32.f16.f16.f32 "
        "{%0,%1,%2,%3}, {%4,%5,%6,%7}, {%8,%9}, {%0,%1,%2,%3};\n"
        : "+f"(d[0]), "+f"(d[1]), "+f"(d[2]), "+f"(d[3])
        : "r"(a[0]), "r"(a[1]), "r"(a[2]), "r"(a[3]), "r"(b[0]), "r"(b[1]));
}

__device__ __forceinline__ unsigned packh2(float lo, float hi) {
    __half2 h = __floats2half2_rn(lo, hi);
    return *(unsigned*)&h;
}

__device__ __forceinline__ void cpasync16(unsigned dst, const void* src) {
    asm volatile("cp.async.cg.shared.global [%0], [%1], 16;\n" :: "r"(dst), "l"(src));
}
#define CP_COMMIT() asm volatile("cp.async.commit_group;\n" ::: "memory")
#define CP_WAIT2()  asm volatile("cp.async.wait_group 2;\n" ::: "memory")

// ---------------------------------------------------------------------------
// LayerNorm: one block per row; writes fp32 AND fp16 outputs
// ---------------------------------------------------------------------------
__global__ void ln_kernel(const float* __restrict__ x, const float* __restrict__ g,
                          const float* __restrict__ b, float* __restrict__ yf,
                          __half* __restrict__ yh) {
    int row = blockIdx.x;
    int tid = threadIdx.x;
    const float* xr = x + (size_t)row * DMODEL;

    float v[4];
    float s = 0.f, s2 = 0.f;
#pragma unroll
    for (int i = 0; i < 4; i++) {
        v[i] = xr[tid + 256 * i];
        s  += v[i];
        s2 += v[i] * v[i];
    }
#pragma unroll
    for (int o = 16; o; o >>= 1) {
        s  += __shfl_xor_sync(0xffffffffu, s,  o);
        s2 += __shfl_xor_sync(0xffffffffu, s2, o);
    }
    __shared__ float ss[8], ss2[8];
    int w = tid >> 5, lane = tid & 31;
    if (lane == 0) { ss[w] = s; ss2[w] = s2; }
    __syncthreads();
    s = 0.f; s2 = 0.f;
#pragma unroll
    for (int i = 0; i < 8; i++) { s += ss[i]; s2 += ss2[i]; }

    float mean = s * (1.f / DMODEL);
    float var  = s2 * (1.f / DMODEL) - mean * mean;
    float rstd = rsqrtf(var + 1e-5f);
#pragma unroll
    for (int i = 0; i < 4; i++) {
        int c = tid + 256 * i;
        float val = (v[i] - mean) * rstd * g[c] + b[c];
        yf[(size_t)row * DMODEL + c] = val;
        yh[(size_t)row * DMODEL + c] = __float2half_rn(val);
    }
}

// ---------------------------------------------------------------------------
// Fused weight conversion: all four weight sets -> interleaved fp16 words
// ---------------------------------------------------------------------------
#define QKV_W  ((DMODEL / 2) * QKV3)
#define PROJ_W ((DMODEL / 2) * DMODEL)
#define W1_W   ((DMODEL / 2) * DFF)
#define W2_W   ((DFF / 2) * DMODEL)
#define CONV_TOTAL (QKV_W + PROJ_W + W1_W + W2_W)

__global__ void conv_all(const float* __restrict__ wq, const float* __restrict__ wk,
                         const float* __restrict__ wv, const float* __restrict__ wproj,
                         const float* __restrict__ w1, const float* __restrict__ w2,
                         unsigned* __restrict__ wqkvi, unsigned* __restrict__ wproji,
                         unsigned* __restrict__ w1i, unsigned* __restrict__ w2i) {
    int idx = blockIdx.x * 256 + threadIdx.x;
    if (idx < QKV_W) {
        int kp = idx / QKV3, n = idx % QKV3;
        int s = n >> 10, nn = n & 1023, h = nn >> 6, e = nn & 63;
        const float* w = (s == 0) ? wq : (s == 1) ? wk : wv;
        float lo = w[(h << 16) + ((2 * kp) << 6) + e];
        float hi = w[(h << 16) + ((2 * kp + 1) << 6) + e];
        wqkvi[idx] = packh2(lo, hi);
        return;
    }
    idx -= QKV_W;
    if (idx < PROJ_W) {
        int kp = idx >> 10, n = idx & 1023;
        wproji[idx] = packh2(wproj[(size_t)(2 * kp) * DMODEL + n],
                             wproj[(size_t)(2 * kp + 1) * DMODEL + n]);
        return;
    }
    idx -= PROJ_W;
    if (idx < W1_W) {
        int kp = idx >> 12, n = idx & 4095;
        w1i[idx] = packh2(w1[(size_t)(2 * kp) * DFF + n],
                          w1[(size_t)(2 * kp + 1) * DFF + n]);
        return;
    }
    idx -= W1_W;
    {
        int kp = idx >> 10, n = idx & 1023;
        w2i[idx] = packh2(w2[(size_t)(2 * kp) * DMODEL + n],
                          w2[(size_t)(2 * kp + 1) * DMODEL + n]);
    }
}

// ---------------------------------------------------------------------------
// FP16 tensor-core GEMM (unchanged from R8 — at mma.sync ceiling).
// CTA tile 128x256, warp tile 64x64, 256 threads, 4-stage cp.async ring.
// ---------------------------------------------------------------------------
#define STAGES 4
#define AW 12
#define BW 264
#define AS_WORDS (128 * AW)
#define BS_WORDS (8 * BW)
#define STG_WORDS (AS_WORDS + BS_WORDS)
#define GEMM_SMEM_BYTES (STAGES * STG_WORDS * 4)   // 58368

template <int EPI, int OUT16>
__global__ __launch_bounds__(256, 1)
void gemm_h(const __half* __restrict__ A, const unsigned* __restrict__ Bi,
            const float* __restrict__ bias, const float* __restrict__ res,
            float* __restrict__ C, __half* __restrict__ C16,
            int M, int N, int K) {
    extern __shared__ unsigned smw[];
    const unsigned sbase = (unsigned)__cvta_generic_to_shared(smw);

    const int t  = threadIdx.x;
    const int bx = blockIdx.x;
    const int by = blockIdx.y;

    const int lane = t & 31;
    const int warp = t >> 5;
    const int wm   = warp >> 2;
    const int wn   = warp & 3;
    const int m0   = wm * 64;
    const int n0   = wn * 64;
    const int g    = lane >> 2;
    const int tig  = lane & 3;

    const int ar  = t >> 1;
    const int aw4 = (t & 1) * 4;
    const int bkp0 = t >> 6,          bw0 = (t & 63) * 4;
    const int bkp1 = (t + 256) >> 6,  bw1 = ((t + 256) & 63) * 4;

    const __half*   Abase = A  + (size_t)(by * 128) * K;
    const unsigned* Bbase = Bi + bx * 256;

    float acc[4][8][4];
#pragma unroll
    for (int mi = 0; mi < 4; mi++)
#pragma unroll
        for (int ni = 0; ni < 8; ni++)
#pragma unroll
            for (int r = 0; r < 4; r++) acc[mi][ni][r] = 0.f;

    const int nTiles = K / 16;

    auto issue = [&](int st, int k0) {
        unsigned ab = sbase + (st * STG_WORDS) * 4;
        unsigned bb = ab + AS_WORDS * 4;
        cpasync16(ab + (ar * AW + aw4) * 4, Abase + (size_t)ar * K + k0 + aw4 * 2);
        cpasync16(bb + (bkp0 * BW + bw0) * 4, Bbase + (size_t)(k0 / 2 + bkp0) * N + bw0);
        cpasync16(bb + (bkp1 * BW + bw1) * 4, Bbase + (size_t)(k0 / 2 + bkp1) * N + bw1);
        CP_COMMIT();
    };

    issue(0, 0);
    issue(1, 16);
    issue(2, 32);
    int lt = 3;

    for (int tt = 0; tt < nTiles; tt++) {
        CP_WAIT2();
        __syncthreads();

        if (lt < nTiles) issue(lt & (STAGES - 1), lt * 16);
        else CP_COMMIT();
        lt++;

        const unsigned* As_ = smw + (tt & (STAGES - 1)) * STG_WORDS;
        const unsigned* Bs_ = As_ + AS_WORDS;

        unsigned af[4][4];
#pragma unroll
        for (int mi = 0; mi < 4; mi++) {
            int m = m0 + mi * 16 + g;
            af[mi][0] = As_[m * AW + tig];
            af[mi][1] = As_[(m + 8) * AW + tig];
            af[mi][2] = As_[m * AW + tig + 4];
            af[mi][3] = As_[(m + 8) * AW + tig + 4];
        }
        unsigned bf[8][2];
#pragma unroll
        for (int ni = 0; ni < 8; ni++) {
            int n = n0 + ni * 8 + g;
            bf[ni][0] = Bs_[tig * BW + n];
            bf[ni][1] = Bs_[(tig + 4) * BW + n];
        }
#pragma unroll
        for (int mi = 0; mi < 4; mi++)
#pragma unroll
            for (int ni = 0; ni < 8; ni++)
                mma_fp16(acc[mi][ni], af[mi], bf[ni]);
    }

    // ---- epilogue ----
#pragma unroll
    for (int mi = 0; mi < 4; mi++) {
#pragma unroll
        for (int ni = 0; ni < 8; ni++) {
            int row = by * 128 + m0 + mi * 16 + g;
            int col = bx * 256 + n0 + ni * 8 + tig * 2;
            float v0 = acc[mi][ni][0];
            float v1 = acc[mi][ni][1];
            float v2 = acc[mi][ni][2];
            float v3 = acc[mi][ni][3];
            if (EPI & 1) {
                float bb0 = bias[col], bb1 = bias[col + 1];
                v0 += bb0; v1 += bb1; v2 += bb0; v3 += bb1;
            }
            if (EPI & 2) {
                v0 = fmaxf(v0, 0.f); v1 = fmaxf(v1, 0.f);
                v2 = fmaxf(v2, 0.f); v3 = fmaxf(v3, 0.f);
            }
            if (EPI & 4) {
                const float* r0 = res + (size_t)row * N + col;
                const float* r1 = r0 + (size_t)8 * N;
                v0 += r0[0]; v1 += r0[1]; v2 += r1[0]; v3 += r1[1];
            }
            if (OUT16) {
                *(unsigned*)(C16 + (size_t)row * N + col)       = packh2(v0, v1);
                *(unsigned*)(C16 + (size_t)(row + 8) * N + col) = packh2(v2, v3);
            } else {
                *(float2*)(C + (size_t)row * N + col)       = make_float2(v0, v1);
                *(float2*)(C + (size_t)(row + 8) * N + col) = make_float2(v2, v3);
            }
        }
    }
}

// ---------------------------------------------------------------------------
// FP16 tensor-core causal flash attention, 128 q-rows per block (8 warps).
// Each K/V tile load is shared by 8 warps (2x the previous amortization).
// Per-warp causal guards; numerics identical to R8.
// ---------------------------------------------------------------------------
#define TS 68

__global__ __launch_bounds__(256)
void attn_h(const __half* __restrict__ QKV, __half* __restrict__ O) {
    __shared__ unsigned Ks[32 * TS];
    __shared__ unsigned Vs[32 * TS];

    const int qb = (gridDim.x - 1) - blockIdx.x;    // heavy blocks first
    const int bh = blockIdx.y;
    const int b  = bh >> 4;
    const int h  = bh & 15;
    const size_t baseQ = (size_t)b * SEQ * QKV3 + (size_t)h * HDIM;
    const size_t baseO = (size_t)b * SEQ * DMODEL + (size_t)h * HDIM;

    const int tid  = threadIdx.x;
    const int lane = tid & 31;
    const int warp = tid >> 5;          // 0..7
    const int g    = lane >> 2;
    const int tig  = lane & 3;
    const int m    = warp * 16;         // warp's q-row offset in 128-row tile
    const int q0   = qb * 128;

    const int row0 = q0 + m + g;
    const int row1 = row0 + 8;

    // ---- Q fragments: direct 32-bit loads from packed-fp16 global ----
    unsigned qf[4][4];
    {
        const unsigned* qr0 = (const unsigned*)(QKV + baseQ + (size_t)row0 * QKV3);
        const unsigned* qr1 = (const unsigned*)(QKV + baseQ + (size_t)row1 * QKV3);
#pragma unroll
        for (int kk = 0; kk < 4; kk++) {
            qf[kk][0] = qr0[kk * 8 + tig];
            qf[kk][1] = qr1[kk * 8 + tig];
            qf[kk][2] = qr0[kk * 8 + tig + 4];
            qf[kk][3] = qr1[kk * 8 + tig + 4];
        }
    }

    float o[8][4];
#pragma unroll
    for (int ni = 0; ni < 8; ni++)
#pragma unroll
        for (int r = 0; r < 4; r++) o[ni][r] = 0.f;
    float mrun0 = -1e30f, mrun1 = -1e30f, lrun0 = 0.f, lrun1 = 0.f;

    const float scale = 0.125f;
    const unsigned qkvW = QKV3 / 2;
    const int kbmax = 2 * qb + 2;       // key blocks covering rows [0, q0+128)

    for (int kb = 0; kb < kbmax; kb++) {
        __syncthreads();
        // ---- load K tile (transpose-pack) + V tile (key-pair interleave) ----
        {
            const unsigned* Kw = (const unsigned*)(QKV) +
                ((baseQ + DMODEL) >> 1) + (size_t)(kb * 64) * qkvW;
#pragma unroll
            for (int it = 0; it < 8; it++) {
                int i = it * 256 + tid;          // 0..2047
                int f = (i >> 2) & 31;
                int r = (i & 3) + ((i >> 7) << 2);
                Ks[f * TS + r] = Kw[(size_t)r * qkvW + f];
            }
            const unsigned* Vw = (const unsigned*)(QKV) +
                ((baseQ + 2 * DMODEL) >> 1) + (size_t)(kb * 64) * qkvW;
#pragma unroll
            for (int it = 0; it < 4; it++) {
                int i   = it * 256 + tid;        // 0..1023
                int fp2 = i & 31;
                int kp  = i >> 5;
                unsigned w0 = Vw[(size_t)(2 * kp)     * qkvW + fp2];
                unsigned w1 = Vw[(size_t)(2 * kp + 1) * qkvW + fp2];
                Vs[kp * TS + 2 * fp2]     = __byte_perm(w0, w1, 0x5410);
                Vs[kp * TS + 2 * fp2 + 1] = __byte_perm(w0, w1, 0x7632);
            }
        }
        __syncthreads();

        // warp-uniform skip: any key in this block usable by this warp?
        if (kb * 64 > q0 + m + 15) continue;

        // ---- S = Q @ K^T ----
        float s[8][4];
#pragma unroll
        for (int ni = 0; ni < 8; ni++)
#pragma unroll
            for (int r = 0; r < 4; r++) s[ni][r] = 0.f;
#pragma unroll
        for (int kk = 0; kk < 4; kk++) {
#pragma unroll
            for (int ni = 0; ni < 8; ni++) {
                unsigned bf[2];
                bf[0] = Ks[(kk * 8 + tig) * TS + ni * 8 + g];
                bf[1] = Ks[(kk * 8 + tig + 4) * TS + ni * 8 + g];
                mma_fp16(s[ni], qf[kk], bf);
            }
        }

        // ---- scale + causal mask (masked path when keys can exceed rows) ----
        if (kb * 64 + 63 > q0 + m) {
#pragma unroll
            for (int ni = 0; ni < 8; ni++) {
                int c0 = kb * 64 + ni * 8 + tig * 2;
                int c1 = c0 + 1;
                s[ni][0] = (c0 <= row0) ? s[ni][0] * scale : -1e30f;
                s[ni][1] = (c1 <= row0) ? s[ni][1] * scale : -1e30f;
                s[ni][2] = (c0 <= row1) ? s[ni][2] * scale : -1e30f;
                s[ni][3] = (c1 <= row1) ? s[ni][3] * scale : -1e30f;
            }
        } else {
#pragma unroll
            for (int ni = 0; ni < 8; ni++) {
                s[ni][0] *= scale; s[ni][1] *= scale;
                s[ni][2] *= scale; s[ni][3] *= scale;
            }
        }

        // ---- online softmax ----
        float mx0 = -1e30f, mx1 = -1e30f;
#pragma unroll
        for (int ni = 0; ni < 8; ni++) {
            mx0 = fmaxf(mx0, fmaxf(s[ni][0], s[ni][1]));
            mx1 = fmaxf(mx1, fmaxf(s[ni][2], s[ni][3]));
        }
        mx0 = fmaxf(mx0, __shfl_xor_sync(0xffffffffu, mx0, 1));
        mx0 = fmaxf(mx0, __shfl_xor_sync(0xffffffffu, mx0, 2));
        mx1 = fmaxf(mx1, __shfl_xor_sync(0xffffffffu, mx1, 1));
        mx1 = fmaxf(mx1, __shfl_xor_sync(0xffffffffu, mx1, 2));

        float mnew0 = fmaxf(mrun0, mx0);
        float mnew1 = fmaxf(mrun1, mx1);
        float corr0 = __expf(mrun0 - mnew0);
        float corr1 = __expf(mrun1 - mnew1);

        float ls0 = 0.f, ls1 = 0.f;
#pragma unroll
        for (int ni = 0; ni < 8; ni++) {
            s[ni][0] = __expf(s[ni][0] - mnew0);
            s[ni][1] = __expf(s[ni][1] - mnew0);
            s[ni][2] = __expf(s[ni][2] - mnew1);
            s[ni][3] = __expf(s[ni][3] - mnew1);
            ls0 += s[ni][0] + s[ni][1];
            ls1 += s[ni][2] + s[ni][3];
        }
        ls0 += __shfl_xor_sync(0xffffffffu, ls0, 1);
        ls0 += __shfl_xor_sync(0xffffffffu, ls0, 2);
        ls1 += __shfl_xor_sync(0xffffffffu, ls1, 1);
        ls1 += __shfl_xor_sync(0xffffffffu, ls1, 2);

        lrun0 = lrun0 * corr0 + ls0;
        lrun1 = lrun1 * corr1 + ls1;
        mrun0 = mnew0;
        mrun1 = mnew1;
#pragma unroll
        for (int ni = 0; ni < 8; ni++) {
            o[ni][0] *= corr0; o[ni][1] *= corr0;
            o[ni][2] *= corr1; o[ni][3] *= corr1;
        }

        // ---- O += P @ V (P packed from registers) ----
#pragma unroll
        for (int kk = 0; kk < 4; kk++) {
            unsigned pf[4];
            pf[0] = packh2(s[2 * kk][0],     s[2 * kk][1]);
            pf[1] = packh2(s[2 * kk][2],     s[2 * kk][3]);
            pf[2] = packh2(s[2 * kk + 1][0], s[2 * kk + 1][1]);
            pf[3] = packh2(s[2 * kk + 1][2], s[2 * kk + 1][3]);
#pragma unroll
            for (int ni = 0; ni < 8; ni++) {
                unsigned vb[2];
                vb[0] = Vs[(kk * 8 + tig) * TS + ni * 8 + g];
                vb[1] = Vs[(kk * 8 + tig + 4) * TS + ni * 8 + g];
                mma_fp16(o[ni], pf, vb);
            }
        }
    }

    // ---- epilogue: normalized fp16 output ----
    float inv0 = 1.f / lrun0;
    float inv1 = 1.f / lrun1;
#pragma unroll
    for (int ni = 0; ni < 8; ni++) {
        int col = ni * 8 + tig * 2;
        *(unsigned*)(O + baseO + (size_t)row0 * DMODEL + col) =
            packh2(o[ni][0] * inv0, o[ni][1] * inv0);
        *(unsigned*)(O + baseO + (size_t)row1 * DMODEL + col) =
            packh2(o[ni][2] * inv1, o[ni][3] * inv1);
    }
}

// ---------------------------------------------------------------------------
// Launch
// ---------------------------------------------------------------------------
extern "C" void kernel_launch(void* const* d_in, const int* in_sizes, int n_in,
                              void* d_out, int out_size) {
    const float* x      = (const float*)d_in[0];
    const float* wq     = (const float*)d_in[1];
    const float* wk     = (const float*)d_in[2];
    const float* wv     = (const float*)d_in[3];
    const float* w_proj = (const float*)d_in[4];
    const float* b_proj = (const float*)d_in[5];
    const float* w1     = (const float*)d_in[6];
    const float* b1     = (const float*)d_in[7];
    const float* w2     = (const float*)d_in[8];
    const float* b2     = (const float*)d_in[9];
    const float* g1     = (const float*)d_in[10];
    const float* be1    = (const float*)d_in[11];
    const float* g2     = (const float*)d_in[12];
    const float* be2    = (const float*)d_in[13];
    float* out = (float*)d_out;

    __half *xn1h, *qkvh, *atth, *xn2h, *hbh;
    float  *xn1f, *x2, *xn2f;
    unsigned *wqkvi, *wproji, *w1i, *w2i;
    cudaGetSymbolAddress((void**)&xn1h,  g_xn1h);
    cudaGetSymbolAddress((void**)&xn1f,  g_xn1f);
    cudaGetSymbolAddress((void**)&qkvh,  g_qkvh);
    cudaGetSymbolAddress((void**)&atth,  g_atth);
    cudaGetSymbolAddress((void**)&x2,    g_x2);
    cudaGetSymbolAddress((void**)&xn2h,  g_xn2h);
    cudaGetSymbolAddress((void**)&xn2f,  g_xn2f);
    cudaGetSymbolAddress((void**)&hbh,   g_hbh);
    cudaGetSymbolAddress((void**)&wqkvi, g_wqkv_i);
    cudaGetSymbolAddress((void**)&wproji,g_wproj_i);
    cudaGetSymbolAddress((void**)&w1i,   g_w1_i);
    cudaGetSymbolAddress((void**)&w2i,   g_w2_i);

    cudaFuncSetAttribute(gemm_h<0,1>, cudaFuncAttributeMaxDynamicSharedMemorySize, GEMM_SMEM_BYTES);
    cudaFuncSetAttribute(gemm_h<3,1>, cudaFuncAttributeMaxDynamicSharedMemorySize, GEMM_SMEM_BYTES);
    cudaFuncSetAttribute(gemm_h<5,0>, cudaFuncAttributeMaxDynamicSharedMemorySize, GEMM_SMEM_BYTES);

    // 1. LN1 (fp32 + fp16 outputs)
    ln_kernel<<<NTOK, 256>>>(x, g1, be1, xn1f, xn1h);

    // 2. all weight conversions, one launch
    conv_all<<<CONV_TOTAL / 256, 256>>>(wq, wk, wv, w_proj, w1, w2,
                                        wqkvi, wproji, w1i, w2i);

    // 3. fused QKV projection -> fp16 packed qkv
    gemm_h<0,1><<<dim3(QKV3 / 256, NTOK / 128), 256, GEMM_SMEM_BYTES>>>(
        xn1h, wqkvi, nullptr, nullptr, nullptr, qkvh, NTOK, QKV3, DMODEL);

    // 4. attention -> fp16 att (128 q-rows per block)
    attn_h<<<dim3(SEQ / 128, BATCH * NHEAD), 256>>>(qkvh, atth);

    // 5. output projection + bias + residual(xn1 fp32) -> x2 fp32
    gemm_h<5,0><<<dim3(DMODEL / 256, NTOK / 128), 256, GEMM_SMEM_BYTES>>>(
        atth, wproji, b_proj, xn1f, x2, nullptr, NTOK, DMODEL, DMODEL);

    // 6. LN2
    ln_kernel<<<NTOK, 256>>>(x2, g2, be2, xn2f, xn2h);

    // 7. FFN up + bias + relu -> fp16 hb
    gemm_h<3,1><<<dim3(DFF / 256, NTOK / 128), 256, GEMM_SMEM_BYTES>>>(
        xn2h, w1i, b1, nullptr, nullptr, hbh, NTOK, DFF, DMODEL);

    // 8. FFN down + bias + residual(xn2 fp32) -> out fp32
    gemm_h<5,0><<<dim3(DMODEL / 256, NTOK / 128), 256, GEMM_SMEM_BYTES>>>(
        hbh, w2i, b2, xn2f, out, nullptr, NTOK, DMODEL, DFF);
}